// round 15
// baseline (speedup 1.0000x reference)
#include <cuda_runtime.h>
#include <cuda_fp16.h>

#define TAB 2048
#define FULLMASK 0xffffffffu
#define EBF 1184           // edge blocks per filter
typedef unsigned long long ull;

__device__ __half2 g_htabd[2][TAB * 128];  // {val, delta} per feature, fp16
__device__ float4  g_einv[1000000];        // per-edge SO3 invariants
__device__ float2  g_etf[1000000];         // per-edge (tf, bitcast ti)

__device__ __forceinline__ float silu_f(float x) {
    float h = 0.5f * x, t;
    asm("tanh.approx.f32 %0, %1;" : "=f"(t) : "f"(h));
    return fmaf(h, t, h);
}
__device__ __forceinline__ float silu_acc(float x) { return __fdividef(x, 1.0f + __expf(-x)); }

__device__ __forceinline__ ull dup2(float x) {
    ull r; unsigned u = __float_as_uint(x);
    asm("mov.b64 %0, {%1,%1};" : "=l"(r) : "r"(u)); return r;
}
__device__ __forceinline__ ull pack2(float a, float b) {
    ull r;
    asm("mov.b64 %0, {%1,%2};" : "=l"(r) : "r"(__float_as_uint(a)), "r"(__float_as_uint(b)));
    return r;
}
__device__ __forceinline__ void fma2(ull &d, ull a, ull b) {
    asm("fma.rn.f32x2 %0, %1, %2, %0;" : "+l"(d) : "l"(a), "l"(b));
}
__device__ __forceinline__ void unpack2(ull v, float &lo, float &hi) {
    unsigned a, b; asm("mov.b64 {%0,%1}, %2;" : "=r"(a), "=r"(b) : "l"(v));
    lo = __uint_as_float(a); hi = __uint_as_float(b);
}

// ===========================================================================
// Setup kernel: [0,128) fp16 (val,delta) table build — register-blocked,
//               w2 streamed ONCE; [128,128+PB) per-edge prep
// ===========================================================================
__global__ void __launch_bounds__(256) setup_kernel(
    const float* __restrict__ evf,
    const int* __restrict__ senders, const int* __restrict__ receivers,
    const float* __restrict__ lengths,
    const float* __restrict__ fi_rbf_w1, const float* __restrict__ fi_rbf_b1,
    const float* __restrict__ fi_rbf_w2, const float* __restrict__ fi_rbf_b2,
    const float* __restrict__ fe_rbf_w1, const float* __restrict__ fe_rbf_b1,
    const float* __restrict__ fe_rbf_w2, const float* __restrict__ fe_rbf_b2,
    int E)
{
    int bid = blockIdx.x;
    int tid = threadIdx.x;

    if (bid < 128) {
        // ---- table build: 64 blocks per filter, 32 output rows/block -------
        // Evaluates 33 rows (need val[row+1] for delta), rg0: rows 0..16,
        // rg1: rows 17..32 of the block's range.
        __shared__ float h1s[33][128];   // 16.9 KB
        __shared__ float vals[33][128];  // 16.9 KB
        int filt = bid >> 6;
        const float* w1 = filt ? fe_rbf_w1 : fi_rbf_w1;
        const float* b1 = filt ? fe_rbf_b1 : fi_rbf_b1;
        const float* w2 = filt ? fe_rbf_w2 : fi_rbf_w2;
        const float* b2 = filt ? fe_rbf_b2 : fi_rbf_b2;
        int f  = tid & 127;
        int rg = tid >> 7;               // 0 or 1
        int rlo = rg ? 17 : 0;
        int rhi = rg ? 33 : 17;          // rg0: 17 rows, rg1: 16 rows
        int r0 = (bid & 63) * 32;

        float w1col[32];
#pragma unroll
        for (int k = 0; k < 32; k++) w1col[k] = __ldg(&w1[k * 128 + f]);
        float b1f = __ldg(&b1[f]), b2f = __ldg(&b2[f]);
        const float step  = 5.0f / 31.0f;
        const float gamma = 0.5f / (step * step);
        const float dx    = 5.0f / (float)(TAB - 1);

        // phase 1: h1 for this rg's rows
        for (int r = rlo; r < rhi; r++) {
            int row = r0 + r; if (row > TAB - 1) row = TAB - 1;
            float x = (float)row * dx;
            float a1 = b1f;
#pragma unroll
            for (int k = 0; k < 32; k++) {
                float d = x - (float)k * step;
                a1 = fmaf(__expf(-gamma * d * d), w1col[k], a1);
            }
            h1s[r][f] = silu_acc(a1);
        }
        __syncthreads();

        // phase 2: stream w2 once, accumulate all rows in registers
        {
            float a2[17];
            int nr = rhi - rlo;
#pragma unroll
            for (int r = 0; r < 17; r++) a2[r] = b2f;
            for (int k = 0; k < 128; k++) {
                float w = __ldg(&w2[k * 128 + f]);
#pragma unroll
                for (int r = 0; r < 17; r++)
                    if (r < nr) a2[r] = fmaf(h1s[rlo + r][k], w, a2[r]);
            }
#pragma unroll
            for (int r = 0; r < 17; r++)
                if (r < nr) vals[rlo + r][f] = silu_acc(a2[r]);
        }
        __syncthreads();

        // phase 3: write (val, delta) fp16 pairs for the 32 output rows
        for (int r = rg ? 16 : 0; r < (rg ? 32 : 16); r++) {
            int row = r0 + r;
            float v = vals[r][f];
            float d = (row < TAB - 1) ? (vals[r + 1][f] - v) : 0.0f;
            g_htabd[filt][(size_t)row * 128 + f] = __floats2half2_rn(v, d);
        }
        return;
    }

    // ---- edge prep: one edge per thread ----
    int e = (bid - 128) * 256 + tid;
    if (e >= E) return;
    const float tscale = (float)(TAB - 1) / 5.0f;
    int sN = __ldg(senders + e), rN = __ldg(receivers + e);
    const float4* As = reinterpret_cast<const float4*>(evf) + (size_t)sN * 4;
    const float4* Ar = reinterpret_cast<const float4*>(evf) + (size_t)rN * 4;
    float4 a, b; float dx, dy, dz, dw;
    float i0, i1, i2, i3;
    a = __ldg(As);     b = __ldg(Ar);     dx = a.x-b.x; dy = a.y-b.y; dz = a.z-b.z; dw = a.w-b.w;
    i0 = dx*dx; i1 = dy*dy + dz*dz + dw*dw;
    a = __ldg(As + 1); b = __ldg(Ar + 1); dx = a.x-b.x; dy = a.y-b.y; dz = a.z-b.z; dw = a.w-b.w;
    i2 = dx*dx + dy*dy + dz*dz + dw*dw;
    a = __ldg(As + 2); b = __ldg(Ar + 2); dx = a.x-b.x; dy = a.y-b.y; dz = a.z-b.z; dw = a.w-b.w;
    i2 += dx*dx; i3 = dy*dy + dz*dz + dw*dw;
    a = __ldg(As + 3); b = __ldg(Ar + 3); dx = a.x-b.x; dy = a.y-b.y; dz = a.z-b.z; dw = a.w-b.w;
    i3 += dx*dx + dy*dy + dz*dz + dw*dw;
    float xf = __ldg(lengths + e) * tscale;
    int ti = (int)xf;
    if (ti < 0) ti = 0; if (ti > TAB - 2) ti = TAB - 2;
    g_einv[e] = make_float4(i0, i1, i2, i3);
    g_etf[e]  = make_float2(xf - (float)ti, __int_as_float(ti));
}

// ===========================================================================
// Main kernel (256 threads, 3 blocks/SM):
//   blocks [0, NB)        : node update (LSU-bound; runs in wave 1, overlaps)
//   blocks [NB, NB+2*EBF) : edge filter nets (filt = (bid-NB)&1)
// ===========================================================================
__global__ void __launch_bounds__(256, 3) main_kernel(
    const float* __restrict__ invf, const float* __restrict__ evf,
    const float* __restrict__ fi_w1, const float* __restrict__ fi_b1,
    const float* __restrict__ fi_w2, const float* __restrict__ fi_b2,
    const float* __restrict__ fe_w1, const float* __restrict__ fe_b1,
    const float* __restrict__ fe_w2, const float* __restrict__ fe_b2,
    const float* __restrict__ w_int, const float* __restrict__ b_int,
    float* __restrict__ out1, float* __restrict__ out2,
    float* __restrict__ fwi, float* __restrict__ fwe,
    int N, int E, int NB)
{
    __shared__ __align__(16) char smbuf[34816];
    int bid = blockIdx.x;
    int tid = threadIdx.x;
    int warp = tid >> 5, lane = tid & 31;

    if (bid >= NB) {
        // =============== EDGE PATH (R8 layout) =============================
        float*  s_we2 = reinterpret_cast<float*>(smbuf);                    // 16384 B
        float2* s_e1  = reinterpret_cast<float2*>(smbuf + 16384);           // 8192 B
        float4* s_edv = reinterpret_cast<float4*>(smbuf + 24576);           // 1024 B
        float2* s_m   = reinterpret_cast<float2*>(smbuf + 25600);           // 512 B

        int eb = bid - NB;
        int filt = eb & 1;
        int ebid = eb >> 1;
        const float* we1 = filt ? fe_w1 : fi_w1; const float* be1 = filt ? fe_b1 : fi_b1;
        const float* we2 = filt ? fe_w2 : fi_w2; const float* be2 = filt ? fe_b2 : fi_b2;
        float* outp = filt ? fwe : fwi;
        const __half2* tabd = g_htabd[filt];

        for (int i = tid; i < 4096; i += 256) s_we2[i] = __ldg(we2 + i);
        __syncthreads();

        float w1l0 = __ldg(we1 + lane),      w1l1 = __ldg(we1 + 32 + lane);
        float w1l2 = __ldg(we1 + 64 + lane), w1l3 = __ldg(we1 + 96 + lane);
        float bl   = __ldg(be1 + lane);
        float4 bb  = __ldg(reinterpret_cast<const float4*>(be2) + lane);
        ull bd0 = dup2(bb.x), bd1 = dup2(bb.y), bd2 = dup2(bb.z), bd3 = dup2(bb.w);
        const float4* wv = reinterpret_cast<const float4*>(s_we2);
        float4* outv = reinterpret_cast<float4*>(outp);

        int gw = ebid * 8 + warp;
        int nwarps = EBF * 8;

        for (int base = gw * 8; base < E; base += nwarps * 8) {
            if (lane < 8) {
                int e = base + lane; if (e >= E) e = E - 1;
                s_edv[warp * 8 + lane] = g_einv[e];
                s_m[warp * 8 + lane]   = g_etf[e];
            }
            __syncwarp();

            // layer 1: hidden = lane, edge pairs into float2
#pragma unroll
            for (int p = 0; p < 4; p++) {
                float4 v0 = s_edv[warp * 8 + 2 * p];
                float4 v1 = s_edv[warp * 8 + 2 * p + 1];
                float ea = silu_f(fmaf(v0.x, w1l0, fmaf(v0.y, w1l1,
                                  fmaf(v0.z, w1l2, fmaf(v0.w, w1l3, bl)))));
                float eb2 = silu_f(fmaf(v1.x, w1l0, fmaf(v1.y, w1l1,
                                  fmaf(v1.z, w1l2, fmaf(v1.w, w1l3, bl)))));
                s_e1[(warp * 4 + p) * 32 + lane] = make_float2(ea, eb2);
            }
            __syncwarp();

            // layer 2: 32 -> 128, f32x2 over edge pairs
            ull acc[4][4];
#pragma unroll
            for (int p = 0; p < 4; p++) { acc[p][0] = bd0; acc[p][1] = bd1; acc[p][2] = bd2; acc[p][3] = bd3; }
            const float4* e1v = reinterpret_cast<const float4*>(s_e1 + warp * 128);
#pragma unroll 2
            for (int k2 = 0; k2 < 16; k2++) {
                float4 wa = wv[(2 * k2) * 32 + lane];
                float4 wb = wv[(2 * k2 + 1) * 32 + lane];
                ull wa0 = dup2(wa.x), wa1 = dup2(wa.y), wa2 = dup2(wa.z), wa3 = dup2(wa.w);
                ull wb0 = dup2(wb.x), wb1 = dup2(wb.y), wb2 = dup2(wb.z), wb3 = dup2(wb.w);
#pragma unroll
                for (int p = 0; p < 4; p++) {
                    float4 cc = e1v[p * 16 + k2];
                    ull c0 = pack2(cc.x, cc.y);
                    ull c1 = pack2(cc.z, cc.w);
                    fma2(acc[p][0], wa0, c0); fma2(acc[p][1], wa1, c0);
                    fma2(acc[p][2], wa2, c0); fma2(acc[p][3], wa3, c0);
                    fma2(acc[p][0], wb0, c1); fma2(acc[p][1], wb1, c1);
                    fma2(acc[p][2], wb2, c1); fma2(acc[p][3], wb3, c1);
                }
            }

            // epilogue: silu + fp16 (val,delta) table fma + store
#pragma unroll
            for (int p = 0; p < 4; p++) {
                float l0, h0, l1, h1, l2, h2, l3, h3;
                unpack2(acc[p][0], l0, h0); unpack2(acc[p][1], l1, h1);
                unpack2(acc[p][2], l2, h2); unpack2(acc[p][3], l3, h3);
#pragma unroll
                for (int hh = 0; hh < 2; hh++) {
                    int j = 2 * p + hh;
                    int e = base + j;
                    if (e < E) {
                        float e0 = hh ? h0 : l0, e1 = hh ? h1 : l1;
                        float e2 = hh ? h2 : l2, e3 = hh ? h3 : l3;
                        float tf = s_m[warp * 8 + j].x;
                        int   ti = __float_as_int(s_m[warp * 8 + j].y);
                        const uint4* tp = reinterpret_cast<const uint4*>(tabd + (size_t)ti * 128) + lane;
                        uint4 u = __ldg(tp);
                        float2 p0 = __half22float2(*reinterpret_cast<__half2*>(&u.x));
                        float2 p1 = __half22float2(*reinterpret_cast<__half2*>(&u.y));
                        float2 p2 = __half22float2(*reinterpret_cast<__half2*>(&u.z));
                        float2 p3 = __half22float2(*reinterpret_cast<__half2*>(&u.w));
                        float4 o;
                        o.x = fmaf(tf, p0.y, p0.x) + silu_f(e0);
                        o.y = fmaf(tf, p1.y, p1.x) + silu_f(e1);
                        o.z = fmaf(tf, p2.y, p2.x) + silu_f(e2);
                        o.w = fmaf(tf, p3.y, p3.x) + silu_f(e3);
                        outv[(size_t)e * 32 + lane] = o;
                    }
                }
            }
            __syncwarp();
        }
        return;
    }

    // =============== NODE PATH (8 nodes/warp, f32x2 pairs) ==================
    float2* xs = reinterpret_cast<float2*>(smbuf);      // [8 warps][4 pairs][136]
    int ngrp = (N + 7) >> 3;
    int grp = bid * 8 + warp;
    if (grp >= ngrp) return;
    int nbase = grp * 8;
    int o4 = (lane < 4) ? (128 + lane) : lane;
    float2* xw = xs + warp * 4 * 136;

    float attv[8];
#pragma unroll
    for (int nd = 0; nd < 8; nd++) {
        int n = nbase + nd; if (n >= N) n = N - 1;
        float* Xp = reinterpret_cast<float*>(xw + (nd >> 1) * 136) + (nd & 1);
#pragma unroll
        for (int j = 0; j < 4; j++)
            Xp[2 * (lane + 32 * j)] = 2.0f * __ldg(invf + (size_t)n * 128 + lane + 32 * j);
        float av = 0.f, dsq = 0.f;
        if (lane < 16) { av = 2.0f * __ldg(evf + (size_t)n * 16 + lane); dsq = av * av; }
        attv[nd] = av;
        float v0 = __shfl_sync(FULLMASK, dsq, 0);
        float v1 = __shfl_sync(FULLMASK, dsq, 1) + __shfl_sync(FULLMASK, dsq, 2)
                 + __shfl_sync(FULLMASK, dsq, 3);
        float v2 = __shfl_sync(FULLMASK, dsq, 4) + __shfl_sync(FULLMASK, dsq, 5)
                 + __shfl_sync(FULLMASK, dsq, 6) + __shfl_sync(FULLMASK, dsq, 7)
                 + __shfl_sync(FULLMASK, dsq, 8);
        float v3 = __shfl_sync(FULLMASK, dsq, 9) + __shfl_sync(FULLMASK, dsq, 10)
                 + __shfl_sync(FULLMASK, dsq, 11) + __shfl_sync(FULLMASK, dsq, 12)
                 + __shfl_sync(FULLMASK, dsq, 13) + __shfl_sync(FULLMASK, dsq, 14)
                 + __shfl_sync(FULLMASK, dsq, 15);
        if (lane == 0) { Xp[2*128] = v0; Xp[2*129] = v1; Xp[2*130] = v2; Xp[2*131] = v3; }
    }
    __syncwarp();

    ull acc[4][5];
    {
        ull d0 = dup2(__ldg(b_int + lane)),      d1 = dup2(__ldg(b_int + 32 + lane));
        ull d2 = dup2(__ldg(b_int + 64 + lane)), d3 = dup2(__ldg(b_int + 96 + lane));
        ull d4 = dup2(__ldg(b_int + o4));
#pragma unroll
        for (int p = 0; p < 4; p++) {
            acc[p][0] = d0; acc[p][1] = d1; acc[p][2] = d2; acc[p][3] = d3; acc[p][4] = d4;
        }
    }
#pragma unroll 2
    for (int i = 0; i < 132; i++) {
        const float* wr = w_int + i * 132;
        ull w0 = dup2(__ldg(wr + lane)),      ww1 = dup2(__ldg(wr + 32 + lane));
        ull w2 = dup2(__ldg(wr + 64 + lane)), w3 = dup2(__ldg(wr + 96 + lane));
        ull w4 = dup2(__ldg(wr + o4));
#pragma unroll
        for (int p = 0; p < 4; p++) {
            ull x = reinterpret_cast<const ull*>(xw + p * 136)[i];
            fma2(acc[p][0], w0, x); fma2(acc[p][1], ww1, x);
            fma2(acc[p][2], w2, x); fma2(acc[p][3], w3, x);
            fma2(acc[p][4], w4, x);
        }
    }
#pragma unroll
    for (int nd = 0; nd < 8; nd++) {
        int n = nbase + nd;
        if (n >= N) break;
        int p = nd >> 1, s = nd & 1;
        const float* Xp = reinterpret_cast<const float*>(xw + p * 136) + s;
        float lo, hi, a0, a1, a2, a3, a4;
        unpack2(acc[p][0], lo, hi); a0 = s ? hi : lo;
        unpack2(acc[p][1], lo, hi); a1 = s ? hi : lo;
        unpack2(acc[p][2], lo, hi); a2 = s ? hi : lo;
        unpack2(acc[p][3], lo, hi); a3 = s ? hi : lo;
        unpack2(acc[p][4], lo, hi); a4 = s ? hi : lo;
        out1[(size_t)n * 128 + lane]      = Xp[2 * (lane)]      + a0;
        out1[(size_t)n * 128 + 32 + lane] = Xp[2 * (32 + lane)] + a1;
        out1[(size_t)n * 128 + 64 + lane] = Xp[2 * (64 + lane)] + a2;
        out1[(size_t)n * 128 + 96 + lane] = Xp[2 * (96 + lane)] + a3;
        float c0 = __shfl_sync(FULLMASK, a4, 0), c1 = __shfl_sync(FULLMASK, a4, 1);
        float c2 = __shfl_sync(FULLMASK, a4, 2), c3 = __shfl_sync(FULLMASK, a4, 3);
        if (lane < 16) {
            float bs = (lane == 0) ? c0 : ((lane < 4) ? c1 : ((lane < 9) ? c2 : c3));
            out2[(size_t)n * 16 + lane] = attv[nd] * (1.0f + bs);
        }
    }
}

// ---------------------------------------------------------------------------
extern "C" void kernel_launch(void* const* d_in, const int* in_sizes, int n_in,
                              void* d_out, int out_size)
{
    const float* invf      = (const float*)d_in[0];
    const float* evf       = (const float*)d_in[1];
    const int*   senders   = (const int*)  d_in[2];
    const int*   receivers = (const int*)  d_in[3];
    const float* lengths   = (const float*)d_in[5];
    const float* fi_rbf_w1 = (const float*)d_in[7];
    const float* fi_rbf_b1 = (const float*)d_in[8];
    const float* fi_rbf_w2 = (const float*)d_in[9];
    const float* fi_rbf_b2 = (const float*)d_in[10];
    const float* fi_ev_w1  = (const float*)d_in[11];
    const float* fi_ev_b1  = (const float*)d_in[12];
    const float* fi_ev_w2  = (const float*)d_in[13];
    const float* fi_ev_b2  = (const float*)d_in[14];
    const float* fe_rbf_w1 = (const float*)d_in[15];
    const float* fe_rbf_b1 = (const float*)d_in[16];
    const float* fe_rbf_w2 = (const float*)d_in[17];
    const float* fe_rbf_b2 = (const float*)d_in[18];
    const float* fe_ev_w1  = (const float*)d_in[19];
    const float* fe_ev_b1  = (const float*)d_in[20];
    const float* fe_ev_w2  = (const float*)d_in[21];
    const float* fe_ev_b2  = (const float*)d_in[22];
    const float* w_int     = (const float*)d_in[23];
    const float* b_int     = (const float*)d_in[24];

    int N = in_sizes[0] / 128;
    int E = in_sizes[5];

    float* out1 = (float*)d_out;
    float* out2 = out1 + (size_t)N * 128;
    float* fwi  = out2 + (size_t)N * 16;
    float* fwe  = fwi  + (size_t)E * 128;

    int PB = (E + 255) / 256;
    int ngrp = (N + 7) / 8;
    int NB = (ngrp + 7) / 8;

    setup_kernel<<<128 + PB, 256>>>(
        evf, senders, receivers, lengths,
        fi_rbf_w1, fi_rbf_b1, fi_rbf_w2, fi_rbf_b2,
        fe_rbf_w1, fe_rbf_b1, fe_rbf_w2, fe_rbf_b2, E);

    main_kernel<<<NB + 2 * EBF, 256>>>(
        invf, evf,
        fi_ev_w1, fi_ev_b1, fi_ev_w2, fi_ev_b2,
        fe_ev_w1, fe_ev_b1, fe_ev_w2, fe_ev_b2,
        w_int, b_int, out1, out2, fwi, fwe, N, E, NB);
}

// round 16
// speedup vs baseline: 1.0254x; 1.0254x over previous
#include <cuda_runtime.h>
#include <cuda_fp16.h>

#define TAB 2048
#define FULLMASK 0xffffffffu
#define EBF 1184           // edge blocks per filter
typedef unsigned long long ull;

__device__ __half2 g_htabd[2][TAB * 128];  // {val, delta} per feature, fp16
__device__ float4  g_einv[1000000];        // per-edge SO3 invariants
__device__ float2  g_etf[1000000];         // per-edge (tf, bitcast ti)

__device__ __forceinline__ float silu_f(float x) {
    float h = 0.5f * x, t;
    asm("tanh.approx.f32 %0, %1;" : "=f"(t) : "f"(h));
    return fmaf(h, t, h);
}
__device__ __forceinline__ float silu_acc(float x) { return __fdividef(x, 1.0f + __expf(-x)); }

__device__ __forceinline__ ull dup2(float x) {
    ull r; unsigned u = __float_as_uint(x);
    asm("mov.b64 %0, {%1,%1};" : "=l"(r) : "r"(u)); return r;
}
__device__ __forceinline__ ull pack2(float a, float b) {
    ull r;
    asm("mov.b64 %0, {%1,%2};" : "=l"(r) : "r"(__float_as_uint(a)), "r"(__float_as_uint(b)));
    return r;
}
__device__ __forceinline__ void fma2(ull &d, ull a, ull b) {
    asm("fma.rn.f32x2 %0, %1, %2, %0;" : "+l"(d) : "l"(a), "l"(b));
}
__device__ __forceinline__ void unpack2(ull v, float &lo, float &hi) {
    unsigned a, b; asm("mov.b64 {%0,%1}, %2;" : "=r"(a), "=r"(b) : "l"(v));
    lo = __uint_as_float(a); hi = __uint_as_float(b);
}

// ===========================================================================
// Setup kernel: [0,128) fp16 (val,delta) table build — register-blocked,
//               w2 streamed ONCE; [128,128+PB) per-edge prep
// ===========================================================================
__global__ void __launch_bounds__(256) setup_kernel(
    const float* __restrict__ evf,
    const int* __restrict__ senders, const int* __restrict__ receivers,
    const float* __restrict__ lengths,
    const float* __restrict__ fi_rbf_w1, const float* __restrict__ fi_rbf_b1,
    const float* __restrict__ fi_rbf_w2, const float* __restrict__ fi_rbf_b2,
    const float* __restrict__ fe_rbf_w1, const float* __restrict__ fe_rbf_b1,
    const float* __restrict__ fe_rbf_w2, const float* __restrict__ fe_rbf_b2,
    int E)
{
    int bid = blockIdx.x;
    int tid = threadIdx.x;

    if (bid < 128) {
        // ---- table build: 64 blocks per filter, 32 output rows/block -------
        __shared__ float h1s[33][128];
        __shared__ float vals[33][128];
        int filt = bid >> 6;
        const float* w1 = filt ? fe_rbf_w1 : fi_rbf_w1;
        const float* b1 = filt ? fe_rbf_b1 : fi_rbf_b1;
        const float* w2 = filt ? fe_rbf_w2 : fi_rbf_w2;
        const float* b2 = filt ? fe_rbf_b2 : fi_rbf_b2;
        int f  = tid & 127;
        int rg = tid >> 7;               // 0 or 1
        int rlo = rg ? 17 : 0;
        int rhi = rg ? 33 : 17;
        int r0 = (bid & 63) * 32;

        float w1col[32];
#pragma unroll
        for (int k = 0; k < 32; k++) w1col[k] = __ldg(&w1[k * 128 + f]);
        float b1f = __ldg(&b1[f]), b2f = __ldg(&b2[f]);
        const float step  = 5.0f / 31.0f;
        const float gamma = 0.5f / (step * step);
        const float dx    = 5.0f / (float)(TAB - 1);

        // phase 1: h1 rows
        for (int r = rlo; r < rhi; r++) {
            int row = r0 + r; if (row > TAB - 1) row = TAB - 1;
            float x = (float)row * dx;
            float a1 = b1f;
#pragma unroll
            for (int k = 0; k < 32; k++) {
                float d = x - (float)k * step;
                a1 = fmaf(__expf(-gamma * d * d), w1col[k], a1);
            }
            h1s[r][f] = silu_acc(a1);
        }
        __syncthreads();

        // phase 2: stream w2 once, row accumulators in registers
        {
            float a2[17];
            int nr = rhi - rlo;
#pragma unroll
            for (int r = 0; r < 17; r++) a2[r] = b2f;
            for (int k = 0; k < 128; k++) {
                float w = __ldg(&w2[k * 128 + f]);
#pragma unroll
                for (int r = 0; r < 17; r++)
                    if (r < nr) a2[r] = fmaf(h1s[rlo + r][k], w, a2[r]);
            }
#pragma unroll
            for (int r = 0; r < 17; r++)
                if (r < nr) vals[rlo + r][f] = silu_acc(a2[r]);
        }
        __syncthreads();

        // phase 3: (val, delta) fp16 pairs
        for (int r = rg ? 16 : 0; r < (rg ? 32 : 16); r++) {
            int row = r0 + r;
            float v = vals[r][f];
            float d = (row < TAB - 1) ? (vals[r + 1][f] - v) : 0.0f;
            g_htabd[filt][(size_t)row * 128 + f] = __floats2half2_rn(v, d);
        }
        return;
    }

    // ---- edge prep: one edge per thread ----
    int e = (bid - 128) * 256 + tid;
    if (e >= E) return;
    const float tscale = (float)(TAB - 1) / 5.0f;
    int sN = __ldg(senders + e), rN = __ldg(receivers + e);
    const float4* As = reinterpret_cast<const float4*>(evf) + (size_t)sN * 4;
    const float4* Ar = reinterpret_cast<const float4*>(evf) + (size_t)rN * 4;
    float4 a, b; float dx, dy, dz, dw;
    float i0, i1, i2, i3;
    a = __ldg(As);     b = __ldg(Ar);     dx = a.x-b.x; dy = a.y-b.y; dz = a.z-b.z; dw = a.w-b.w;
    i0 = dx*dx; i1 = dy*dy + dz*dz + dw*dw;
    a = __ldg(As + 1); b = __ldg(Ar + 1); dx = a.x-b.x; dy = a.y-b.y; dz = a.z-b.z; dw = a.w-b.w;
    i2 = dx*dx + dy*dy + dz*dz + dw*dw;
    a = __ldg(As + 2); b = __ldg(Ar + 2); dx = a.x-b.x; dy = a.y-b.y; dz = a.z-b.z; dw = a.w-b.w;
    i2 += dx*dx; i3 = dy*dy + dz*dz + dw*dw;
    a = __ldg(As + 3); b = __ldg(Ar + 3); dx = a.x-b.x; dy = a.y-b.y; dz = a.z-b.z; dw = a.w-b.w;
    i3 += dx*dx + dy*dy + dz*dz + dw*dw;
    float xf = __ldg(lengths + e) * tscale;
    int ti = (int)xf;
    if (ti < 0) ti = 0; if (ti > TAB - 2) ti = TAB - 2;
    g_einv[e] = make_float4(i0, i1, i2, i3);
    g_etf[e]  = make_float2(xf - (float)ti, __int_as_float(ti));
}

// ===========================================================================
// Main kernel (256 threads, 3 blocks/SM) — R14-proven ordering:
//   blocks [0, 2*EBF)  : edge filter nets (filt = bid&1)
//   blocks [2*EBF, +NB): node update (fills tail waves / idle LSU slots)
// ===========================================================================
__global__ void __launch_bounds__(256, 3) main_kernel(
    const float* __restrict__ invf, const float* __restrict__ evf,
    const float* __restrict__ fi_w1, const float* __restrict__ fi_b1,
    const float* __restrict__ fi_w2, const float* __restrict__ fi_b2,
    const float* __restrict__ fe_w1, const float* __restrict__ fe_b1,
    const float* __restrict__ fe_w2, const float* __restrict__ fe_b2,
    const float* __restrict__ w_int, const float* __restrict__ b_int,
    float* __restrict__ out1, float* __restrict__ out2,
    float* __restrict__ fwi, float* __restrict__ fwe,
    int N, int E)
{
    __shared__ __align__(16) char smbuf[34816];
    int bid = blockIdx.x;
    int tid = threadIdx.x;
    int warp = tid >> 5, lane = tid & 31;

    if (bid < 2 * EBF) {
        // =============== EDGE PATH =========================================
        float*  s_we2 = reinterpret_cast<float*>(smbuf);                    // 16384 B
        float2* s_e1  = reinterpret_cast<float2*>(smbuf + 16384);           // 8192 B
        float4* s_edv = reinterpret_cast<float4*>(smbuf + 24576);           // 1024 B
        float2* s_m   = reinterpret_cast<float2*>(smbuf + 25600);           // 512 B

        int filt = bid & 1;
        int ebid = bid >> 1;
        const float* we1 = filt ? fe_w1 : fi_w1; const float* be1 = filt ? fe_b1 : fi_b1;
        const float* we2 = filt ? fe_w2 : fi_w2; const float* be2 = filt ? fe_b2 : fi_b2;
        float* outp = filt ? fwe : fwi;
        const __half2* tabd = g_htabd[filt];

        for (int i = tid; i < 4096; i += 256) s_we2[i] = __ldg(we2 + i);
        __syncthreads();

        float w1l0 = __ldg(we1 + lane),      w1l1 = __ldg(we1 + 32 + lane);
        float w1l2 = __ldg(we1 + 64 + lane), w1l3 = __ldg(we1 + 96 + lane);
        float bl   = __ldg(be1 + lane);
        float4 bb  = __ldg(reinterpret_cast<const float4*>(be2) + lane);
        ull bd0 = dup2(bb.x), bd1 = dup2(bb.y), bd2 = dup2(bb.z), bd3 = dup2(bb.w);
        const float4* wv = reinterpret_cast<const float4*>(s_we2);
        float4* outv = reinterpret_cast<float4*>(outp);

        int gw = ebid * 8 + warp;
        int nwarps = EBF * 8;

        for (int base = gw * 8; base < E; base += nwarps * 8) {
            if (lane < 8) {
                int e = base + lane; if (e >= E) e = E - 1;
                s_edv[warp * 8 + lane] = g_einv[e];
                s_m[warp * 8 + lane]   = g_etf[e];
            }
            __syncwarp();

            // layer 1: hidden = lane, edge pairs into float2
#pragma unroll
            for (int p = 0; p < 4; p++) {
                float4 v0 = s_edv[warp * 8 + 2 * p];
                float4 v1 = s_edv[warp * 8 + 2 * p + 1];
                float ea = silu_f(fmaf(v0.x, w1l0, fmaf(v0.y, w1l1,
                                  fmaf(v0.z, w1l2, fmaf(v0.w, w1l3, bl)))));
                float eb2 = silu_f(fmaf(v1.x, w1l0, fmaf(v1.y, w1l1,
                                  fmaf(v1.z, w1l2, fmaf(v1.w, w1l3, bl)))));
                s_e1[(warp * 4 + p) * 32 + lane] = make_float2(ea, eb2);
            }
            __syncwarp();

            // layer 2: 32 -> 128, f32x2 over edge pairs
            ull acc[4][4];
#pragma unroll
            for (int p = 0; p < 4; p++) { acc[p][0] = bd0; acc[p][1] = bd1; acc[p][2] = bd2; acc[p][3] = bd3; }
            const float4* e1v = reinterpret_cast<const float4*>(s_e1 + warp * 128);
#pragma unroll 2
            for (int k2 = 0; k2 < 16; k2++) {
                float4 wa = wv[(2 * k2) * 32 + lane];
                float4 wb = wv[(2 * k2 + 1) * 32 + lane];
                ull wa0 = dup2(wa.x), wa1 = dup2(wa.y), wa2 = dup2(wa.z), wa3 = dup2(wa.w);
                ull wb0 = dup2(wb.x), wb1 = dup2(wb.y), wb2 = dup2(wb.z), wb3 = dup2(wb.w);
#pragma unroll
                for (int p = 0; p < 4; p++) {
                    float4 cc = e1v[p * 16 + k2];
                    ull c0 = pack2(cc.x, cc.y);
                    ull c1 = pack2(cc.z, cc.w);
                    fma2(acc[p][0], wa0, c0); fma2(acc[p][1], wa1, c0);
                    fma2(acc[p][2], wa2, c0); fma2(acc[p][3], wa3, c0);
                    fma2(acc[p][0], wb0, c1); fma2(acc[p][1], wb1, c1);
                    fma2(acc[p][2], wb2, c1); fma2(acc[p][3], wb3, c1);
                }
            }

            // epilogue: silu + fp16 (val,delta) table fma + store
#pragma unroll
            for (int p = 0; p < 4; p++) {
                float l0, h0, l1, h1, l2, h2, l3, h3;
                unpack2(acc[p][0], l0, h0); unpack2(acc[p][1], l1, h1);
                unpack2(acc[p][2], l2, h2); unpack2(acc[p][3], l3, h3);
#pragma unroll
                for (int hh = 0; hh < 2; hh++) {
                    int j = 2 * p + hh;
                    int e = base + j;
                    if (e < E) {
                        float e0 = hh ? h0 : l0, e1 = hh ? h1 : l1;
                        float e2 = hh ? h2 : l2, e3 = hh ? h3 : l3;
                        float tf = s_m[warp * 8 + j].x;
                        int   ti = __float_as_int(s_m[warp * 8 + j].y);
                        const uint4* tp = reinterpret_cast<const uint4*>(tabd + (size_t)ti * 128) + lane;
                        uint4 u = __ldg(tp);
                        float2 p0 = __half22float2(*reinterpret_cast<__half2*>(&u.x));
                        float2 p1 = __half22float2(*reinterpret_cast<__half2*>(&u.y));
                        float2 p2 = __half22float2(*reinterpret_cast<__half2*>(&u.z));
                        float2 p3 = __half22float2(*reinterpret_cast<__half2*>(&u.w));
                        float4 o;
                        o.x = fmaf(tf, p0.y, p0.x) + silu_f(e0);
                        o.y = fmaf(tf, p1.y, p1.x) + silu_f(e1);
                        o.z = fmaf(tf, p2.y, p2.x) + silu_f(e2);
                        o.w = fmaf(tf, p3.y, p3.x) + silu_f(e3);
                        outv[(size_t)e * 32 + lane] = o;
                    }
                }
            }
            __syncwarp();
        }
        return;
    }

    // =============== NODE PATH (8 nodes/warp, f32x2 pairs) ==================
    float2* xs = reinterpret_cast<float2*>(smbuf);      // [8 warps][4 pairs][136]
    int ngrp = (N + 7) >> 3;
    int grp = (bid - 2 * EBF) * 8 + warp;
    if (grp >= ngrp) return;
    int nbase = grp * 8;
    int o4 = (lane < 4) ? (128 + lane) : lane;
    float2* xw = xs + warp * 4 * 136;

    float attv[8];
#pragma unroll
    for (int nd = 0; nd < 8; nd++) {
        int n = nbase + nd; if (n >= N) n = N - 1;
        float* Xp = reinterpret_cast<float*>(xw + (nd >> 1) * 136) + (nd & 1);
#pragma unroll
        for (int j = 0; j < 4; j++)
            Xp[2 * (lane + 32 * j)] = 2.0f * __ldg(invf + (size_t)n * 128 + lane + 32 * j);
        float av = 0.f, dsq = 0.f;
        if (lane < 16) { av = 2.0f * __ldg(evf + (size_t)n * 16 + lane); dsq = av * av; }
        attv[nd] = av;
        float v0 = __shfl_sync(FULLMASK, dsq, 0);
        float v1 = __shfl_sync(FULLMASK, dsq, 1) + __shfl_sync(FULLMASK, dsq, 2)
                 + __shfl_sync(FULLMASK, dsq, 3);
        float v2 = __shfl_sync(FULLMASK, dsq, 4) + __shfl_sync(FULLMASK, dsq, 5)
                 + __shfl_sync(FULLMASK, dsq, 6) + __shfl_sync(FULLMASK, dsq, 7)
                 + __shfl_sync(FULLMASK, dsq, 8);
        float v3 = __shfl_sync(FULLMASK, dsq, 9) + __shfl_sync(FULLMASK, dsq, 10)
                 + __shfl_sync(FULLMASK, dsq, 11) + __shfl_sync(FULLMASK, dsq, 12)
                 + __shfl_sync(FULLMASK, dsq, 13) + __shfl_sync(FULLMASK, dsq, 14)
                 + __shfl_sync(FULLMASK, dsq, 15);
        if (lane == 0) { Xp[2*128] = v0; Xp[2*129] = v1; Xp[2*130] = v2; Xp[2*131] = v3; }
    }
    __syncwarp();

    ull acc[4][5];
    {
        ull d0 = dup2(__ldg(b_int + lane)),      d1 = dup2(__ldg(b_int + 32 + lane));
        ull d2 = dup2(__ldg(b_int + 64 + lane)), d3 = dup2(__ldg(b_int + 96 + lane));
        ull d4 = dup2(__ldg(b_int + o4));
#pragma unroll
        for (int p = 0; p < 4; p++) {
            acc[p][0] = d0; acc[p][1] = d1; acc[p][2] = d2; acc[p][3] = d3; acc[p][4] = d4;
        }
    }
#pragma unroll 2
    for (int i = 0; i < 132; i++) {
        const float* wr = w_int + i * 132;
        ull w0 = dup2(__ldg(wr + lane)),      ww1 = dup2(__ldg(wr + 32 + lane));
        ull w2 = dup2(__ldg(wr + 64 + lane)), w3 = dup2(__ldg(wr + 96 + lane));
        ull w4 = dup2(__ldg(wr + o4));
#pragma unroll
        for (int p = 0; p < 4; p++) {
            ull x = reinterpret_cast<const ull*>(xw + p * 136)[i];
            fma2(acc[p][0], w0, x); fma2(acc[p][1], ww1, x);
            fma2(acc[p][2], w2, x); fma2(acc[p][3], w3, x);
            fma2(acc[p][4], w4, x);
        }
    }
#pragma unroll
    for (int nd = 0; nd < 8; nd++) {
        int n = nbase + nd;
        if (n >= N) break;
        int p = nd >> 1, s = nd & 1;
        const float* Xp = reinterpret_cast<const float*>(xw + p * 136) + s;
        float lo, hi, a0, a1, a2, a3, a4;
        unpack2(acc[p][0], lo, hi); a0 = s ? hi : lo;
        unpack2(acc[p][1], lo, hi); a1 = s ? hi : lo;
        unpack2(acc[p][2], lo, hi); a2 = s ? hi : lo;
        unpack2(acc[p][3], lo, hi); a3 = s ? hi : lo;
        unpack2(acc[p][4], lo, hi); a4 = s ? hi : lo;
        out1[(size_t)n * 128 + lane]      = Xp[2 * (lane)]      + a0;
        out1[(size_t)n * 128 + 32 + lane] = Xp[2 * (32 + lane)] + a1;
        out1[(size_t)n * 128 + 64 + lane] = Xp[2 * (64 + lane)] + a2;
        out1[(size_t)n * 128 + 96 + lane] = Xp[2 * (96 + lane)] + a3;
        float c0 = __shfl_sync(FULLMASK, a4, 0), c1 = __shfl_sync(FULLMASK, a4, 1);
        float c2 = __shfl_sync(FULLMASK, a4, 2), c3 = __shfl_sync(FULLMASK, a4, 3);
        if (lane < 16) {
            float bs = (lane == 0) ? c0 : ((lane < 4) ? c1 : ((lane < 9) ? c2 : c3));
            out2[(size_t)n * 16 + lane] = attv[nd] * (1.0f + bs);
        }
    }
}

// ---------------------------------------------------------------------------
extern "C" void kernel_launch(void* const* d_in, const int* in_sizes, int n_in,
                              void* d_out, int out_size)
{
    const float* invf      = (const float*)d_in[0];
    const float* evf       = (const float*)d_in[1];
    const int*   senders   = (const int*)  d_in[2];
    const int*   receivers = (const int*)  d_in[3];
    const float* lengths   = (const float*)d_in[5];
    const float* fi_rbf_w1 = (const float*)d_in[7];
    const float* fi_rbf_b1 = (const float*)d_in[8];
    const float* fi_rbf_w2 = (const float*)d_in[9];
    const float* fi_rbf_b2 = (const float*)d_in[10];
    const float* fi_ev_w1  = (const float*)d_in[11];
    const float* fi_ev_b1  = (const float*)d_in[12];
    const float* fi_ev_w2  = (const float*)d_in[13];
    const float* fi_ev_b2  = (const float*)d_in[14];
    const float* fe_rbf_w1 = (const float*)d_in[15];
    const float* fe_rbf_b1 = (const float*)d_in[16];
    const float* fe_rbf_w2 = (const float*)d_in[17];
    const float* fe_rbf_b2 = (const float*)d_in[18];
    const float* fe_ev_w1  = (const float*)d_in[19];
    const float* fe_ev_b1  = (const float*)d_in[20];
    const float* fe_ev_w2  = (const float*)d_in[21];
    const float* fe_ev_b2  = (const float*)d_in[22];
    const float* w_int     = (const float*)d_in[23];
    const float* b_int     = (const float*)d_in[24];

    int N = in_sizes[0] / 128;
    int E = in_sizes[5];

    float* out1 = (float*)d_out;
    float* out2 = out1 + (size_t)N * 128;
    float* fwi  = out2 + (size_t)N * 16;
    float* fwe  = fwi  + (size_t)E * 128;

    int PB = (E + 255) / 256;
    int ngrp = (N + 7) / 8;
    int NB = (ngrp + 7) / 8;

    setup_kernel<<<128 + PB, 256>>>(
        evf, senders, receivers, lengths,
        fi_rbf_w1, fi_rbf_b1, fi_rbf_w2, fi_rbf_b2,
        fe_rbf_w1, fe_rbf_b1, fe_rbf_w2, fe_rbf_b2, E);

    main_kernel<<<2 * EBF + NB, 256>>>(
        invf, evf,
        fi_ev_w1, fi_ev_b1, fi_ev_w2, fi_ev_b2,
        fe_ev_w1, fe_ev_b1, fe_ev_w2, fe_ev_b2,
        w_int, b_int, out1, out2, fwi, fwe, N, E);
}